// round 13
// baseline (speedup 1.0000x reference)
#include <cuda_runtime.h>
#include <math.h>
#include <stdint.h>

#define NBLK 256
#define BT_LL  32768LL
#define BTV_LL 16777216LL
#define PS_W 47185920
#define PS_X 16777216
#define PS_H 786432
#define PS_L 32768

// ---- scratch (static device globals) ----
__device__ float g_w[141557760];     // 3 planes x 6-layer concat [KT_l][4096] K-major
__device__ float g_x[50331648];      // 3 planes x [128][256][512]
__device__ float g_he[2359296];      // 3 planes x (3 layers x 2 parity x [128,1024])
__device__ float g_hd[2359296];
__device__ float g_c_enc[393216];
__device__ float g_c_dec[393216];
__device__ float g_lat[98304];       // 3 planes x [128,256]
__device__ float g_z[6291456];       // 3 layer slabs x 4 K-partials x [128,4096]
__device__ float g_y[33554432];
__device__ float g_logits[16777216];
__device__ unsigned g_bar_count, g_bar_phase;

__constant__ int c_wbase[6] = {0, 6291456, 14680064, 23068672, 30408704, 38797312};
__constant__ int c_KT[6]    = {1536, 2048, 2048, 1792, 2048, 2048};
__constant__ int c_K1[6]    = {512, 1024, 1024, 768, 1024, 1024};

struct Params {
    const float* b[6];
    const float* w_mean; const float* b_mean;
    const float* w_sigma; const float* b_sigma;
    const float* eps;
};
struct WSrc { const float* wx[6]; const float* wh[6]; };

__device__ __forceinline__ float4 ldf4(const float* p) { return *reinterpret_cast<const float4*>(p); }
__device__ __forceinline__ float4 ldcg4(const float* p) {
    float4 v;
    asm volatile("ld.global.cg.v4.f32 {%0,%1,%2,%3},[%4];"
                 : "=f"(v.x), "=f"(v.y), "=f"(v.z), "=f"(v.w) : "l"(p) : "memory");
    return v;
}
__device__ __forceinline__ float ldcg1(const float* p) {
    float v; asm volatile("ld.global.cg.f32 %0,[%1];" : "=f"(v) : "l"(p) : "memory"); return v;
}
__device__ __forceinline__ unsigned atom_add_acqrel(unsigned* p, unsigned v) {
    unsigned o; asm volatile("atom.add.acq_rel.gpu.global.u32 %0,[%1],%2;" : "=r"(o) : "l"(p), "r"(v) : "memory"); return o;
}
__device__ __forceinline__ void atom_add_release(unsigned* p, unsigned v) {
    unsigned o; asm volatile("atom.add.release.gpu.global.u32 %0,[%1],%2;" : "=r"(o) : "l"(p), "r"(v) : "memory");
}
__device__ __forceinline__ unsigned ld_acquire(const unsigned* p) {
    unsigned v; asm volatile("ld.acquire.gpu.global.u32 %0,[%1];" : "=r"(v) : "l"(p) : "memory"); return v;
}
__device__ __forceinline__ void st_relaxed(unsigned* p, unsigned v) {
    asm volatile("st.relaxed.gpu.global.u32 [%0],%1;" :: "l"(p), "r"(v) : "memory");
}
// Grid barrier (validated R4-R12). 256 blocks co-resident: regs<=128,
// smem 76.8KB x2 = 153.6KB <= 228KB -> 2 blocks/SM.
__device__ __forceinline__ void grid_barrier() {
    __syncthreads();
    if (threadIdx.x == 0) {
        unsigned gen = ld_acquire(&g_bar_phase);
        if (atom_add_acqrel(&g_bar_count, 1u) == NBLK - 1u) {
            st_relaxed(&g_bar_count, 0u);
            atom_add_release(&g_bar_phase, 1u);
        } else {
            while (ld_acquire(&g_bar_phase) == gen) {}
        }
    }
    __syncthreads();
}
// 3-way tf32 split: x = s1+s2+s3 exactly (33 bits >= fp32's 24)
__device__ __forceinline__ float3 tf32_split3(float x) {
    uint32_t b1, b2, b3;
    asm("cvt.rna.tf32.f32 %0, %1;" : "=r"(b1) : "f"(x));
    float s1 = __uint_as_float(b1);
    float r = x - s1;
    asm("cvt.rna.tf32.f32 %0, %1;" : "=r"(b2) : "f"(r));
    float s2 = __uint_as_float(b2);
    asm("cvt.rna.tf32.f32 %0, %1;" : "=r"(b3) : "f"(r - s2));
    return make_float3(s1, s2, __uint_as_float(b3));
}
__device__ __forceinline__ void mma8(float* c, const uint32_t* a, const uint32_t* b) {
    asm volatile("mma.sync.aligned.m16n8k8.row.col.f32.tf32.tf32.f32 "
                 "{%0,%1,%2,%3}, {%4,%5,%6,%7}, {%8,%9}, {%0,%1,%2,%3};"
                 : "+f"(c[0]), "+f"(c[1]), "+f"(c[2]), "+f"(c[3])
                 : "r"(a[0]), "r"(a[1]), "r"(a[2]), "r"(a[3]), "r"(b[0]), "r"(b[1]));
}

// A fetch (validated R10-R12): mode1 [x|h]; mode0 [h1|h2]; mode2 [lat|x|h]
__device__ __forceinline__ float4 afetch4(int mode, const float* xp,
    const float* a1p, const float* a2p, int b, int t, int gk)
{
    if (mode == 0) {
        if (gk < 1024) return ldcg4(a1p + b * 1024 + gk);
        return ldcg4(a2p + b * 1024 + (gk - 1024));
    }
    if (mode == 1) {
        if (gk < 512) return ldf4(xp + ((size_t)b * 256 + t) * 512 + gk);
        return ldcg4(a2p + b * 1024 + (gk - 512));
    }
    if (gk < 256) return ldcg4(a1p + b * 256 + gk);
    if (gk < 768) return ldf4(xp + ((size_t)b * 256 + t) * 512 + (gk - 256));
    return ldcg4(a2p + b * 1024 + (gk - 768));
}

// One layer-step GEMM: tf32 emulation, ALL 6 mmas into a ZEROED sub-acc per
// k8/fragment, merged into acc with RN fadds. Removes tensor-core RZ-chain
// bias (R12's residual): per-mma RZ now applies only to its own 8-product
// slice -> bias ~1e-6 per z, fp32-class end-to-end.
// BM128 x BN64, split-K x4, BK=32. z partial -> [row][4096] at kp slab.
__device__ __noinline__ void gemm_step(
    float* sm, int bid, int mode, int layer,
    const float* xb, const float* a1b, int a1s, const float* a2b,
    float* zslab, int t)
{
    const int tid = threadIdx.x;
    const int col0 = (bid & 63) * 64;
    const int kp = bid >> 6;
    const int kq4 = c_KT[layer] >> 2;
    const int kbase = kp * kq4;
    const float* wbase = g_w + c_wbase[layer];
    zslab += kp * 524288;

    const int w = tid >> 5, lane = tid & 31;
    const int mw = w & 3, nw = w >> 2;
    const int rb = mw * 32, nb = nw * 32;
    const int r = lane >> 2, cq = lane & 3;

    float acc[2][4][4];
#pragma unroll
    for (int mt = 0; mt < 2; mt++)
#pragma unroll
        for (int ntl = 0; ntl < 4; ntl++)
#pragma unroll
            for (int e = 0; e < 4; e++) acc[mt][ntl][e] = 0.0f;

    const int ntile = kq4 >> 5;
    for (int it = 0; it < ntile; it++) {
        const int k0 = kbase + it * 32;
        __syncthreads();
#pragma unroll
        for (int pl = 0; pl < 3; pl++) {               // A 128x32 per plane
            const float* xp  = xb  ? xb  + pl * PS_X : nullptr;
            const float* a1p = a1b ? a1b + pl * a1s  : nullptr;
            const float* a2p = a2b + pl * PS_H;
            float* As = sm + pl * 4224;
            for (int i = tid; i < 1024; i += 256) {
                int row = i >> 3, kq = (i & 7) << 2;
                float4 v = afetch4(mode, xp, a1p, a2p, row, t, k0 + kq);
                As[(kq + 0) * 132 + row] = v.x; As[(kq + 1) * 132 + row] = v.y;
                As[(kq + 2) * 132 + row] = v.z; As[(kq + 3) * 132 + row] = v.w;
            }
        }
#pragma unroll
        for (int pl = 0; pl < 3; pl++) {               // B 32x64 per plane
            const float* wp = wbase + (size_t)pl * PS_W;
            float* Bs = sm + 12672 + pl * 2176;
            for (int i = tid; i < 512; i += 256) {
                int kk = i >> 4, nq = (i & 15) << 2;
                *reinterpret_cast<float4*>(Bs + kk * 68 + nq) =
                    ldf4(wp + (size_t)(k0 + kk) * 4096 + col0 + nq);
            }
        }
        __syncthreads();
        const uint32_t* uA = (const uint32_t*)sm;
        const uint32_t* uB = (const uint32_t*)(sm + 12672);
#pragma unroll
        for (int ks = 0; ks < 4; ks++) {
            const int k8 = ks * 8;
            uint32_t af[3][2][4];
#pragma unroll
            for (int pl = 0; pl < 3; pl++) {
                const uint32_t* a = uA + pl * 4224;
#pragma unroll
                for (int mt = 0; mt < 2; mt++) {
                    int rr = rb + 16 * mt + r;
                    int o0 = (k8 + cq) * 132 + rr, o1 = (k8 + cq + 4) * 132 + rr;
                    af[pl][mt][0] = a[o0]; af[pl][mt][1] = a[o0 + 8];
                    af[pl][mt][2] = a[o1]; af[pl][mt][3] = a[o1 + 8];
                }
            }
#pragma unroll
            for (int ntl = 0; ntl < 4; ntl++) {
                int cc = nb + 8 * ntl + r;
                uint32_t bf[3][2];
#pragma unroll
                for (int pl = 0; pl < 3; pl++) {
                    const uint32_t* b = uB + pl * 2176;
                    bf[pl][0] = b[(k8 + cq) * 68 + cc];
                    bf[pl][1] = b[(k8 + cq + 4) * 68 + cc];
                }
#pragma unroll
                for (int mt = 0; mt < 2; mt++) {
                    // ALL terms (main + 5 corrections) into a FRESH sub-acc;
                    // merge into acc via RN fadds -> no RZ-chain bias.
                    float ct[4] = {0.f, 0.f, 0.f, 0.f};
                    mma8(ct, af[0][mt], bf[0]);   // main s1y1
                    mma8(ct, af[0][mt], bf[1]);
                    mma8(ct, af[1][mt], bf[0]);
                    mma8(ct, af[1][mt], bf[1]);
                    mma8(ct, af[0][mt], bf[2]);
                    mma8(ct, af[2][mt], bf[0]);
                    acc[mt][ntl][0] += ct[0];
                    acc[mt][ntl][1] += ct[1];
                    acc[mt][ntl][2] += ct[2];
                    acc[mt][ntl][3] += ct[3];
                }
            }
        }
    }
#pragma unroll
    for (int mt = 0; mt < 2; mt++)
#pragma unroll
        for (int ntl = 0; ntl < 4; ntl++) {
            int row = rb + 16 * mt + r;
            int col = col0 + nb + 8 * ntl + 2 * cq;
            *reinterpret_cast<float2*>(zslab + (size_t)row * 4096 + col) =
                make_float2(acc[mt][ntl][0], acc[mt][ntl][1]);
            *reinterpret_cast<float2*>(zslab + (size_t)(row + 8) * 4096 + col) =
                make_float2(acc[mt][ntl][2], acc[mt][ntl][3]);
        }
    __syncthreads();
}

// Cell (validated math; 4 K-partials summed); writes h 3-plane split.
__device__ __forceinline__ void cell_step(
    int gid0, const float* __restrict__ zbase,
    float* __restrict__ hb, float* __restrict__ c,
    const float* __restrict__ bias, float* __restrict__ y, int t)
{
#pragma unroll
    for (int it = 0; it < 2; it++) {
        int idx = gid0 + it * 65536;
        int b = idx >> 10, u = idx & 1023;
        size_t zo = (size_t)b * 4096;
        float zi = __ldg(&bias[u]),        zf = __ldg(&bias[1024 + u]);
        float zg = __ldg(&bias[2048 + u]), zon = __ldg(&bias[3072 + u]);
#pragma unroll
        for (int pp = 0; pp < 4; pp++) {
            const float* Zp = zbase + pp * 524288 + zo;
            zi += ldcg1(Zp + u);
            zf += ldcg1(Zp + 1024 + u);
            zg += ldcg1(Zp + 2048 + u);
            zon += ldcg1(Zp + 3072 + u);
        }
        float si = 1.0f / (1.0f + expf(-zi));
        float sf = 1.0f / (1.0f + expf(-zf));
        float so = 1.0f / (1.0f + expf(-zon));
        float cc = sf * c[idx] + si * tanhf(zg);
        c[idx] = cc;
        float hh = so * tanhf(cc);
        float3 s = tf32_split3(hh);
        hb[idx] = s.x; hb[PS_H + idx] = s.y; hb[2 * PS_H + idx] = s.z;
        if (y) y[((size_t)b * 256 + t) * 1024 + u] = hh;
    }
}

__global__ void __launch_bounds__(256, 2) vae_persistent(Params p)
{
    extern __shared__ float sm[];
    const int bid = blockIdx.x, tid = threadIdx.x;
    const int gid0 = bid * 256 + tid;

    for (int i = gid0; i < 2359296; i += NBLK * 256) { g_he[i] = 0.f; g_hd[i] = 0.f; }
    for (int i = gid0; i < 393216; i += NBLK * 256) { g_c_enc[i] = 0.f; g_c_dec[i] = 0.f; }
    grid_barrier();

    float* const z0 = g_z;
    float* const z1 = g_z + 2097152;
    float* const z2 = g_z + 4194304;

    for (int s = 0; s < 258; s++) {                // encoder wavefronts
        const int pw = s & 1, pr = pw ^ 1;
        if (s < 256)
            gemm_step(sm, bid, 1, 0, g_x, nullptr, 0, g_he + pr * 131072, z0, s);
        if (s >= 1 && s <= 256)
            gemm_step(sm, bid, 0, 1, nullptr, g_he + pr * 131072, PS_H,
                      g_he + (2 + pr) * 131072, z1, s - 1);
        if (s >= 2)
            gemm_step(sm, bid, 0, 2, nullptr, g_he + (2 + pr) * 131072, PS_H,
                      g_he + (4 + pr) * 131072, z2, s - 2);
        grid_barrier();
        if (s < 256)
            cell_step(gid0, z0, g_he + pw * 131072, g_c_enc, p.b[0], nullptr, s);
        if (s >= 1 && s <= 256)
            cell_step(gid0, z1, g_he + (2 + pw) * 131072, g_c_enc + 131072, p.b[1], nullptr, s - 1);
        if (s >= 2)
            cell_step(gid0, z2, g_he + (4 + pw) * 131072, g_c_enc + 262144, p.b[2], nullptr, s - 2);
        grid_barrier();
    }

    if (bid < 128) {   // latent: projects CELL state c3; eps ADDED (faithful)
        const float* c3 = g_c_enc + 262144 + bid * 1024;
        for (int i = tid; i < 1024; i += 256) sm[i] = ldcg1(c3 + i);
        __syncthreads();
        float am = 0.f, as = 0.f;
        for (int k = 0; k < 1024; k++) {
            float a = sm[k];
            am = fmaf(a, __ldg(&p.w_mean[k * 256 + tid]), am);
            as = fmaf(a, __ldg(&p.w_sigma[k * 256 + tid]), as);
        }
        float lat = am + __ldg(&p.b_mean[tid]) + expf(0.5f * (as + __ldg(&p.b_sigma[tid])))
                  + __ldg(&p.eps[bid * 256 + tid]);
        float3 s3 = tf32_split3(lat);
        g_lat[bid * 256 + tid] = s3.x;
        g_lat[PS_L + bid * 256 + tid] = s3.y;
        g_lat[2 * PS_L + bid * 256 + tid] = s3.z;
        __syncthreads();
    }
    grid_barrier();

    for (int s = 0; s < 258; s++) {                // decoder wavefronts
        const int pw = s & 1, pr = pw ^ 1;
        if (s < 256)
            gemm_step(sm, bid, 2, 3, g_x, g_lat, PS_L, g_hd + pr * 131072, z0, s);
        if (s >= 1 && s <= 256)
            gemm_step(sm, bid, 0, 4, nullptr, g_hd + pr * 131072, PS_H,
                      g_hd + (2 + pr) * 131072, z1, s - 1);
        if (s >= 2)
            gemm_step(sm, bid, 0, 5, nullptr, g_hd + (2 + pr) * 131072, PS_H,
                      g_hd + (4 + pr) * 131072, z2, s - 2);
        grid_barrier();
        if (s < 256)
            cell_step(gid0, z0, g_hd + pw * 131072, g_c_dec, p.b[3], nullptr, s);
        if (s >= 1 && s <= 256)
            cell_step(gid0, z1, g_hd + (2 + pw) * 131072, g_c_dec + 131072, p.b[4], nullptr, s - 1);
        if (s >= 2)
            cell_step(gid0, z2, g_hd + (4 + pw) * 131072, g_c_dec + 262144, p.b[5], g_y, s - 2);
        grid_barrier();
    }
}

// weights -> concat K-major 3-plane tf32 split
__global__ void prep_w(WSrc w)
{
    long long idx = (long long)blockIdx.x * 256 + threadIdx.x;
    if (idx >= 47185920LL) return;
    int layer = 5;
#pragma unroll
    for (int l = 0; l < 5; l++) if (idx < c_wbase[l + 1]) { layer = l; break; }
    long long rem = idx - c_wbase[layer];
    int n = (int)(rem & 4095), k = (int)(rem >> 12);
    int K1 = c_K1[layer];
    float v = (k < K1) ? w.wx[layer][(size_t)k * 4096 + n]
                       : w.wh[layer][(size_t)(k - K1) * 4096 + n];
    float3 s = tf32_split3(v);
    g_w[idx] = s.x; g_w[PS_W + idx] = s.y; g_w[2LL * PS_W + idx] = s.z;
}
__global__ void prep_x(const int* tokens, const float* emb)
{
    int idx = blockIdx.x * 256 + threadIdx.x;
    int b = idx >> 17, t = (idx >> 9) & 255, v = idx & 511;
    float3 s = tf32_split3(emb[(size_t)tokens[b * 256 + t] * 512 + v]);
    g_x[idx] = s.x; g_x[PS_X + idx] = s.y; g_x[2 * PS_X + idx] = s.z;
}

// Dense logits GEMM (validated R4-R12): Z[32768,512] = Y @ W[1024,512] + b.
__global__ void __launch_bounds__(128) logits_gemm(
    const float* __restrict__ A, const float* __restrict__ W,
    const float* __restrict__ bias, float* __restrict__ Z)
{
    __shared__ __align__(16) float As[16][68];
    __shared__ __align__(16) float Bs[16][64];
    const int tid = threadIdx.x;
    const int tx = tid & 15, ty = tid >> 4;
    const int row0 = blockIdx.y * 64, col0 = blockIdx.x * 64;
    float4 pa[2], pb[2];
#pragma unroll
    for (int j = 0; j < 2; j++) {
        int c = tid + j * 128;
        pa[j] = ldf4(A + (size_t)(row0 + (c >> 2)) * 1024 + (c & 3) * 4);
        pb[j] = ldf4(W + (size_t)(c >> 4) * 512 + col0 + (c & 15) * 4);
    }
#pragma unroll
    for (int j = 0; j < 2; j++) {
        int c = tid + j * 128;
        int m = c >> 2, kb = (c & 3) * 4;
        As[kb + 0][m] = pa[j].x; As[kb + 1][m] = pa[j].y;
        As[kb + 2][m] = pa[j].z; As[kb + 3][m] = pa[j].w;
        *reinterpret_cast<float4*>(&Bs[c >> 4][(c & 15) * 4]) = pb[j];
    }
    __syncthreads();
    float acc[8][4];
#pragma unroll
    for (int r = 0; r < 8; r++)
#pragma unroll
        for (int c2 = 0; c2 < 4; c2++) acc[r][c2] = 0.0f;
    for (int k0 = 16;; k0 += 16) {
        const bool more = (k0 < 1024);
        if (more) {
#pragma unroll
            for (int j = 0; j < 2; j++) {
                int c = tid + j * 128;
                pa[j] = ldf4(A + (size_t)(row0 + (c >> 2)) * 1024 + k0 + (c & 3) * 4);
                pb[j] = ldf4(W + (size_t)(k0 + (c >> 4)) * 512 + col0 + (c & 15) * 4);
            }
        }
#pragma unroll
        for (int kk = 0; kk < 16; kk++) {
            float4 a0 = ldf4(&As[kk][ty * 8]);
            float4 a1 = ldf4(&As[kk][ty * 8 + 4]);
            float4 b  = ldf4(&Bs[kk][tx * 4]);
            float av[8] = {a0.x, a0.y, a0.z, a0.w, a1.x, a1.y, a1.z, a1.w};
            float bv[4] = {b.x, b.y, b.z, b.w};
#pragma unroll
            for (int r = 0; r < 8; r++)
#pragma unroll
                for (int c2 = 0; c2 < 4; c2++)
                    acc[r][c2] = fmaf(av[r], bv[c2], acc[r][c2]);
        }
        if (!more) break;
        __syncthreads();
#pragma unroll
        for (int j = 0; j < 2; j++) {
            int c = tid + j * 128;
            int m = c >> 2, kb = (c & 3) * 4;
            As[kb + 0][m] = pa[j].x; As[kb + 1][m] = pa[j].y;
            As[kb + 2][m] = pa[j].z; As[kb + 3][m] = pa[j].w;
            *reinterpret_cast<float4*>(&Bs[c >> 4][(c & 15) * 4]) = pb[j];
        }
        __syncthreads();
    }
    float4 bv4 = ldf4(bias + col0 + tx * 4);
#pragma unroll
    for (int r = 0; r < 8; r++) {
        float4 v = make_float4(acc[r][0] + bv4.x, acc[r][1] + bv4.y,
                               acc[r][2] + bv4.z, acc[r][3] + bv4.w);
        *reinterpret_cast<float4*>(Z + (size_t)(row0 + ty * 8 + r) * 512 + col0 + tx * 4) = v;
    }
}

// argmax (first-occurrence) + logits emission (validated R4-R12).
__global__ void emit_kernel(const float* __restrict__ logits,
                            float* __restrict__ out, long long out_size)
{
    int row = blockIdx.x, tid = threadIdx.x;
    const float* lr = logits + (size_t)row * 512;
    float best = -3.402823466e38f; int bi = 0;
#pragma unroll
    for (int j = 0; j < 4; j++) {
        int vi = tid + j * 128; float v = lr[vi];
        if (v > best) { best = v; bi = vi; }
    }
    __shared__ float sv[128]; __shared__ int si[128];
    sv[tid] = best; si[tid] = bi;
    __syncthreads();
    for (int s = 64; s > 0; s >>= 1) {
        if (tid < s) {
            float v2 = sv[tid + s]; int i2 = si[tid + s];
            if (v2 > sv[tid] || (v2 == sv[tid] && i2 < si[tid])) { sv[tid] = v2; si[tid] = i2; }
        }
        __syncthreads();
    }
    int amax = si[0];
    if (out_size == BT_LL + BTV_LL) {
        if (tid == 0) out[row] = (float)amax;
        float* lo = out + BT_LL + (size_t)row * 512;
#pragma unroll
        for (int j = 0; j < 4; j++) lo[tid + j * 128] = lr[tid + j * 128];
    } else if (out_size == BTV_LL) {
        float* lo = out + (size_t)row * 512;
#pragma unroll
        for (int j = 0; j < 4; j++) lo[tid + j * 128] = lr[tid + j * 128];
    } else if (out_size == BT_LL) {
        if (tid == 0) reinterpret_cast<int*>(out)[row] = amax;
    } else {
        if (tid == 0 && (long long)row < out_size) out[row] = (float)amax;
#pragma unroll
        for (int j = 0; j < 4; j++) {
            long long o = BT_LL + (long long)row * 512 + tid + j * 128;
            if (o < out_size) out[o] = lr[tid + j * 128];
        }
    }
}

extern "C" void kernel_launch(void* const* d_in, const int* in_sizes, int n_in,
                              void* d_out, int out_size)
{
    WSrc w;
    Params p;
    const int* tokens = (const int*)d_in[0];
    const float* emb  = (const float*)d_in[1];
    for (int l = 0; l < 6; l++) {
        w.wx[l] = (const float*)d_in[2 + l * 3];
        w.wh[l] = (const float*)d_in[3 + l * 3];
        p.b[l]  = (const float*)d_in[4 + l * 3];
    }
    p.w_mean  = (const float*)d_in[20];
    p.b_mean  = (const float*)d_in[21];
    p.w_sigma = (const float*)d_in[22];
    p.b_sigma = (const float*)d_in[23];
    const float* dec_w = (const float*)d_in[24];
    const float* dec_b = (const float*)d_in[25];
    p.eps = (const float*)d_in[26];

    float *y, *lg;
    cudaGetSymbolAddress((void**)&y,  g_y);
    cudaGetSymbolAddress((void**)&lg, g_logits);
    cudaFuncSetAttribute(vae_persistent, cudaFuncAttributeMaxDynamicSharedMemorySize, 76800);

    prep_w<<<184320, 256>>>(w);
    prep_x<<<65536, 256>>>(tokens, emb);
    vae_persistent<<<NBLK, 256, 76800>>>(p);
    logits_gemm<<<dim3(8, 512), 128>>>(y, dec_w, dec_b, lg);
    emit_kernel<<<32768, 128>>>(lg, (float*)d_out, (long long)out_size);
}

// round 14
// speedup vs baseline: 3.3633x; 3.3633x over previous
#include <cuda_runtime.h>
#include <math.h>

#define NBLK 256
#define BT_LL  32768LL          // B*T
#define BTV_LL 16777216LL       // B*T*V

// ---------------- scratch (static device globals; no allocation) -------------
__device__ float g_xd[16777216];     // pre-gathered emb[tokens]: [128][256][512]
__device__ float g_h_enc[786432];    // 3 layers x 2 parity x [128,1024]
__device__ float g_c_enc[393216];    // 3 layers x [128,1024]
__device__ float g_h_dec[786432];
__device__ float g_c_dec[393216];
__device__ float g_z[6291456];       // 3 layer slabs x 4 K-partials x [128,4096]
__device__ float g_lat[32768];       // [128,256]
__device__ float g_y[33554432];      // [128,256,1024] decoder top-layer h
__device__ float g_logits[16777216]; // [128,256,512]
__device__ unsigned g_bar_count, g_bar_phase;

struct Params {
    const float* Wx[6]; const float* Wh[6]; const float* b[6];
    const float* w_mean; const float* b_mean;
    const float* w_sigma; const float* b_sigma;
    const float* eps;
};

__device__ __forceinline__ float4 ldf4(const float* p) {
    return *reinterpret_cast<const float4*>(p);
}
__device__ __forceinline__ float4 ldcg4(const float* p) {
    float4 v;
    asm volatile("ld.global.cg.v4.f32 {%0,%1,%2,%3},[%4];"
                 : "=f"(v.x), "=f"(v.y), "=f"(v.z), "=f"(v.w) : "l"(p) : "memory");
    return v;
}
__device__ __forceinline__ float ldcg1(const float* p) {
    float v; asm volatile("ld.global.cg.f32 %0,[%1];" : "=f"(v) : "l"(p) : "memory");
    return v;
}
__device__ __forceinline__ unsigned atom_add_acqrel(unsigned* p, unsigned v) {
    unsigned o; asm volatile("atom.add.acq_rel.gpu.global.u32 %0,[%1],%2;"
                             : "=r"(o) : "l"(p), "r"(v) : "memory"); return o;
}
__device__ __forceinline__ void atom_add_release(unsigned* p, unsigned v) {
    unsigned o; asm volatile("atom.add.release.gpu.global.u32 %0,[%1],%2;"
                             : "=r"(o) : "l"(p), "r"(v) : "memory");
}
__device__ __forceinline__ unsigned ld_acquire(const unsigned* p) {
    unsigned v; asm volatile("ld.acquire.gpu.global.u32 %0,[%1];"
                             : "=r"(v) : "l"(p) : "memory"); return v;
}
__device__ __forceinline__ void st_relaxed(unsigned* p, unsigned v) {
    asm volatile("st.relaxed.gpu.global.u32 [%0],%1;" :: "l"(p), "r"(v) : "memory");
}

// Grid barrier (validated R4-R13). 256 blocks co-resident: launch_bounds(256,2)
// caps regs at 128 (2*256*128 = 64K RF); static smem 49KB x2 = 98KB <= 228KB.
__device__ __forceinline__ void grid_barrier() {
    __syncthreads();
    if (threadIdx.x == 0) {
        unsigned gen = ld_acquire(&g_bar_phase);
        if (atom_add_acqrel(&g_bar_count, 1u) == NBLK - 1u) {
            st_relaxed(&g_bar_count, 0u);
            atom_add_release(&g_bar_phase, 1u);
        } else {
            while (ld_acquire(&g_bar_phase) == gen) {}
        }
    }
    __syncthreads();
}

// A-operand fetch (R7-validated semantics; x pre-gathered into g_xd):
//   mode 0: A1 dense h [128,1024];  mode 1: A1 = xd[gm,t,:] (K1=512)
//   mode 2: A1 = [g_lat[gm,:] (256) | xd (512)] (K1=768).  A2 = prev-parity h.
__device__ __forceinline__ float4 fetchA(
    int mode, int K1, const float* A1, const float* A2,
    const float* __restrict__ xd, int t, int gm, int gk)
{
    if (gk >= K1) return ldcg4(A2 + gm * 1024 + (gk - K1));
    if (mode == 0) return ldcg4(A1 + gm * 1024 + gk);
    if (mode == 1) return ldf4(xd + ((size_t)gm * 256 + t) * 512 + gk);
    if (gk < 256) return ldcg4(g_lat + gm * 256 + gk);
    return ldf4(xd + ((size_t)gm * 256 + t) * 512 + (gk - 256));
}

// Split-K x4 GEMM (R6/R7-validated tile: BM128 x BN64, 8x4/thread), now with
// BK=32 double-buffered smem -> one __syncthreads per 32-k tile (half of R7).
__device__ void gemm_step(
    float* sA, float* sB, int bid, int mode, int K1, int KT,
    const float* __restrict__ Wx, const float* __restrict__ Wh,
    const float* A1, const float* A2, float* __restrict__ Z,
    int t, const float* __restrict__ xd)
{
    const int tid = threadIdx.x;
    const int part = bid >> 6;
    const int col0 = (bid & 63) * 64;
    const int kq4 = KT >> 2;              // 384 / 512 / 448 (all /32)
    const int kbase = part * kq4;
    Z += part * 524288;

    const int tx = tid & 15, ty = tid >> 4;
    const int mA0 = tid >> 2;             // 0..63 (other half +64)
    const int kqA = (tid & 3) * 4;        // 0,4,8,12 (other half +16)
    const int kkB = tid >> 4, nqB = tid & 15;  // B rows kkB, kkB+16

    float4 a00, a01, a10, a11, b0, b1;

    // ---- prefetch + store k-tile 0 (k 0..31) into buffer 0 ----
    a00 = fetchA(mode, K1, A1, A2, xd, t, mA0,      kbase + kqA);
    a01 = fetchA(mode, K1, A1, A2, xd, t, mA0 + 64, kbase + kqA);
    a10 = fetchA(mode, K1, A1, A2, xd, t, mA0,      kbase + 16 + kqA);
    a11 = fetchA(mode, K1, A1, A2, xd, t, mA0 + 64, kbase + 16 + kqA);
    {
        int gk = kbase + kkB;
        b0 = ldf4(((gk < K1) ? Wx + (size_t)gk * 4096
                             : Wh + (size_t)(gk - K1) * 4096) + col0 + nqB * 4);
        int gk2 = gk + 16;
        b1 = ldf4(((gk2 < K1) ? Wx + (size_t)gk2 * 4096
                              : Wh + (size_t)(gk2 - K1) * 4096) + col0 + nqB * 4);
    }
    {
        float* pa = sA;
        pa[(kqA + 0) * 132 + mA0] = a00.x; pa[(kqA + 1) * 132 + mA0] = a00.y;
        pa[(kqA + 2) * 132 + mA0] = a00.z; pa[(kqA + 3) * 132 + mA0] = a00.w;
        pa[(kqA + 0) * 132 + mA0 + 64] = a01.x; pa[(kqA + 1) * 132 + mA0 + 64] = a01.y;
        pa[(kqA + 2) * 132 + mA0 + 64] = a01.z; pa[(kqA + 3) * 132 + mA0 + 64] = a01.w;
        pa[(16 + kqA + 0) * 132 + mA0] = a10.x; pa[(16 + kqA + 1) * 132 + mA0] = a10.y;
        pa[(16 + kqA + 2) * 132 + mA0] = a10.z; pa[(16 + kqA + 3) * 132 + mA0] = a10.w;
        pa[(16 + kqA + 0) * 132 + mA0 + 64] = a11.x; pa[(16 + kqA + 1) * 132 + mA0 + 64] = a11.y;
        pa[(16 + kqA + 2) * 132 + mA0 + 64] = a11.z; pa[(16 + kqA + 3) * 132 + mA0 + 64] = a11.w;
        *reinterpret_cast<float4*>(sB + kkB * 64 + nqB * 4) = b0;
        *reinterpret_cast<float4*>(sB + (kkB + 16) * 64 + nqB * 4) = b1;
    }
    __syncthreads();

    float acc[8][4];
#pragma unroll
    for (int r = 0; r < 8; r++)
#pragma unroll
        for (int c2 = 0; c2 < 4; c2++) acc[r][c2] = 0.0f;

    const int nt = kq4 >> 5;
    for (int it = 0; it < nt; it++) {
        const int cur = it & 1;
        const bool more = (it + 1 < nt);
        if (more) {
            const int k0 = kbase + (it + 1) * 32;
            a00 = fetchA(mode, K1, A1, A2, xd, t, mA0,      k0 + kqA);
            a01 = fetchA(mode, K1, A1, A2, xd, t, mA0 + 64, k0 + kqA);
            a10 = fetchA(mode, K1, A1, A2, xd, t, mA0,      k0 + 16 + kqA);
            a11 = fetchA(mode, K1, A1, A2, xd, t, mA0 + 64, k0 + 16 + kqA);
            int gk = k0 + kkB;
            b0 = ldf4(((gk < K1) ? Wx + (size_t)gk * 4096
                                 : Wh + (size_t)(gk - K1) * 4096) + col0 + nqB * 4);
            int gk2 = gk + 16;
            b1 = ldf4(((gk2 < K1) ? Wx + (size_t)gk2 * 4096
                                  : Wh + (size_t)(gk2 - K1) * 4096) + col0 + nqB * 4);
        }
        const float* pa = sA + cur * 4224;
        const float* pb = sB + cur * 2048;
#pragma unroll
        for (int kk = 0; kk < 32; kk++) {
            float4 av0 = ldf4(pa + kk * 132 + ty * 8);
            float4 av1 = ldf4(pa + kk * 132 + ty * 8 + 4);
            float4 bv4 = ldf4(pb + kk * 64 + tx * 4);
            float av[8] = {av0.x, av0.y, av0.z, av0.w, av1.x, av1.y, av1.z, av1.w};
            float bv[4] = {bv4.x, bv4.y, bv4.z, bv4.w};
#pragma unroll
            for (int r = 0; r < 8; r++)
#pragma unroll
                for (int c2 = 0; c2 < 4; c2++)
                    acc[r][c2] = fmaf(av[r], bv[c2], acc[r][c2]);
        }
        if (more) {
            float* pa2 = sA + (cur ^ 1) * 4224;
            pa2[(kqA + 0) * 132 + mA0] = a00.x; pa2[(kqA + 1) * 132 + mA0] = a00.y;
            pa2[(kqA + 2) * 132 + mA0] = a00.z; pa2[(kqA + 3) * 132 + mA0] = a00.w;
            pa2[(kqA + 0) * 132 + mA0 + 64] = a01.x; pa2[(kqA + 1) * 132 + mA0 + 64] = a01.y;
            pa2[(kqA + 2) * 132 + mA0 + 64] = a01.z; pa2[(kqA + 3) * 132 + mA0 + 64] = a01.w;
            pa2[(16 + kqA + 0) * 132 + mA0] = a10.x; pa2[(16 + kqA + 1) * 132 + mA0] = a10.y;
            pa2[(16 + kqA + 2) * 132 + mA0] = a10.z; pa2[(16 + kqA + 3) * 132 + mA0] = a10.w;
            pa2[(16 + kqA + 0) * 132 + mA0 + 64] = a11.x; pa2[(16 + kqA + 1) * 132 + mA0 + 64] = a11.y;
            pa2[(16 + kqA + 2) * 132 + mA0 + 64] = a11.z; pa2[(16 + kqA + 3) * 132 + mA0 + 64] = a11.w;
            float* pb2 = sB + (cur ^ 1) * 2048;
            *reinterpret_cast<float4*>(pb2 + kkB * 64 + nqB * 4) = b0;
            *reinterpret_cast<float4*>(pb2 + (kkB + 16) * 64 + nqB * 4) = b1;
        }
        __syncthreads();
    }

#pragma unroll
    for (int r = 0; r < 8; r++) {
        float4 v = make_float4(acc[r][0], acc[r][1], acc[r][2], acc[r][3]);
        *reinterpret_cast<float4*>(
            Z + (size_t)(ty * 8 + r) * 4096 + col0 + tx * 4) = v;
    }
}

// Cell phase (R7-validated math; float4-vectorized). Threads gid0<32768 each
// own one float4 group (b = gid0>>8, u = (gid0&255)*4) -- fixed ownership.
__device__ __forceinline__ void cell_step(
    int gid0, const float* __restrict__ zbase,
    float* __restrict__ h, float* __restrict__ c,
    const float* __restrict__ bias, float* __restrict__ y, int t)
{
    if (gid0 >= 32768) return;
    const int b = gid0 >> 8;
    const int u = (gid0 & 255) * 4;
    const size_t zo = (size_t)b * 4096;
    float4 zi = ldf4(bias + u);
    float4 zf = ldf4(bias + 1024 + u);
    float4 zg = ldf4(bias + 2048 + u);
    float4 zn = ldf4(bias + 3072 + u);
#pragma unroll
    for (int pp = 0; pp < 4; pp++) {
        const float* Zp = zbase + pp * 524288 + zo;
        float4 v;
        v = ldcg4(Zp + u);        zi.x += v.x; zi.y += v.y; zi.z += v.z; zi.w += v.w;
        v = ldcg4(Zp + 1024 + u); zf.x += v.x; zf.y += v.y; zf.z += v.z; zf.w += v.w;
        v = ldcg4(Zp + 2048 + u); zg.x += v.x; zg.y += v.y; zg.z += v.z; zg.w += v.w;
        v = ldcg4(Zp + 3072 + u); zn.x += v.x; zn.y += v.y; zn.z += v.z; zn.w += v.w;
    }
    const int ihc = b * 1024 + u;
    float4 cv = ldf4(c + ihc);
    float4 hv;
    {
        float* zip = &zi.x; float* zfp = &zf.x; float* zgp = &zg.x; float* znp = &zn.x;
        float* cp = &cv.x; float* hp = &hv.x;
#pragma unroll
        for (int e = 0; e < 4; e++) {
            float si = 1.0f / (1.0f + expf(-zip[e]));
            float sf = 1.0f / (1.0f + expf(-zfp[e]));
            float so = 1.0f / (1.0f + expf(-znp[e]));
            float cc = sf * cp[e] + si * tanhf(zgp[e]);
            cp[e] = cc;
            hp[e] = so * tanhf(cc);
        }
    }
    *reinterpret_cast<float4*>(c + ihc) = cv;
    *reinterpret_cast<float4*>(h + ihc) = hv;
    if (y) *reinterpret_cast<float4*>(y + ((size_t)b * 256 + t) * 1024 + u) = hv;
}

// Persistent kernel: wavefront-pipelined (R7-validated scheduler).
__global__ void __launch_bounds__(256, 2) vae_persistent(Params p)
{
    __shared__ __align__(16) float sA[8448];  // 2 x 32 x 132
    __shared__ __align__(16) float sB[4096];  // 2 x 32 x 64

    const int bid = blockIdx.x;
    const int tid = threadIdx.x;
    const int gid0 = bid * 256 + tid;

    for (int i = gid0; i < 786432; i += NBLK * 256) {
        g_h_enc[i] = 0.0f; g_h_dec[i] = 0.0f;
    }
    for (int i = gid0; i < 393216; i += NBLK * 256) {
        g_c_enc[i] = 0.0f; g_c_dec[i] = 0.0f;
    }
    grid_barrier();

    float* const z0 = g_z;
    float* const z1 = g_z + 2097152;
    float* const z2 = g_z + 4194304;

    for (int s = 0; s < 258; s++) {                // encoder wavefronts
        const int pw = s & 1, pr = pw ^ 1;
        if (s < 256)
            gemm_step(sA, sB, bid, 1, 512, 1536, p.Wx[0], p.Wh[0],
                      nullptr, g_h_enc + pr * 131072, z0, s, g_xd);
        if (s >= 1 && s <= 256)
            gemm_step(sA, sB, bid, 0, 1024, 2048, p.Wx[1], p.Wh[1],
                      g_h_enc + pr * 131072, g_h_enc + (2 + pr) * 131072,
                      z1, s - 1, g_xd);
        if (s >= 2)
            gemm_step(sA, sB, bid, 0, 1024, 2048, p.Wx[2], p.Wh[2],
                      g_h_enc + (2 + pr) * 131072, g_h_enc + (4 + pr) * 131072,
                      z2, s - 2, g_xd);
        grid_barrier();
        if (s < 256)
            cell_step(gid0, z0, g_h_enc + pw * 131072, g_c_enc, p.b[0], nullptr, s);
        if (s >= 1 && s <= 256)
            cell_step(gid0, z1, g_h_enc + (2 + pw) * 131072, g_c_enc + 131072,
                      p.b[1], nullptr, s - 1);
        if (s >= 2)
            cell_step(gid0, z2, g_h_enc + (4 + pw) * 131072, g_c_enc + 262144,
                      p.b[2], nullptr, s - 2);
        grid_barrier();
    }

    if (bid < 128) {   // latent: projects CELL state c3; eps ADDED (faithful)
        const float* c3 = g_c_enc + 262144 + bid * 1024;
        for (int i = tid; i < 1024; i += 256) sA[i] = ldcg1(c3 + i);
        __syncthreads();
        float am = 0.f, as = 0.f;
        for (int k = 0; k < 1024; k++) {
            float a = sA[k];
            am = fmaf(a, __ldg(&p.w_mean[k * 256 + tid]), am);
            as = fmaf(a, __ldg(&p.w_sigma[k * 256 + tid]), as);
        }
        float mean = am + __ldg(&p.b_mean[tid]);
        float sg   = as + __ldg(&p.b_sigma[tid]);
        g_lat[bid * 256 + tid] = mean + expf(0.5f * sg)
                               + __ldg(&p.eps[bid * 256 + tid]);
        __syncthreads();
    }
    grid_barrier();

    for (int s = 0; s < 258; s++) {                // decoder wavefronts
        const int pw = s & 1, pr = pw ^ 1;
        if (s < 256)
            gemm_step(sA, sB, bid, 2, 768, 1792, p.Wx[3], p.Wh[3],
                      nullptr, g_h_dec + pr * 131072, z0, s, g_xd);
        if (s >= 1 && s <= 256)
            gemm_step(sA, sB, bid, 0, 1024, 2048, p.Wx[4], p.Wh[4],
                      g_h_dec + pr * 131072, g_h_dec + (2 + pr) * 131072,
                      z1, s - 1, g_xd);
        if (s >= 2)
            gemm_step(sA, sB, bid, 0, 1024, 2048, p.Wx[5], p.Wh[5],
                      g_h_dec + (2 + pr) * 131072, g_h_dec + (4 + pr) * 131072,
                      z2, s - 2, g_xd);
        grid_barrier();
        if (s < 256)
            cell_step(gid0, z0, g_h_dec + pw * 131072, g_c_dec, p.b[3], nullptr, s);
        if (s >= 1 && s <= 256)
            cell_step(gid0, z1, g_h_dec + (2 + pw) * 131072, g_c_dec + 131072,
                      p.b[4], nullptr, s - 1);
        if (s >= 2)
            cell_step(gid0, z2, g_h_dec + (4 + pw) * 131072, g_c_dec + 262144,
                      p.b[5], g_y, s - 2);
        grid_barrier();
    }
}

// pre-gather embeddings: g_xd[b][t][v] = emb[tokens[b][t]][v]
__global__ void prep_x(const int* __restrict__ tokens, const float* __restrict__ emb)
{
    int idx = blockIdx.x * 256 + threadIdx.x;       // float4 index, 4194304 total
    int b = idx >> 15, t = (idx >> 7) & 255, v4 = idx & 127;
    int tok = __ldg(&tokens[b * 256 + t]);
    *reinterpret_cast<float4*>(g_xd + (size_t)idx * 4) =
        ldf4(emb + (size_t)tok * 512 + v4 * 4);
}

// Dense logits GEMM (validated R4-R13): Z[32768,512] = Y @ W[1024,512] + b.
__global__ void __launch_bounds__(128) logits_gemm(
    const float* __restrict__ A, const float* __restrict__ W,
    const float* __restrict__ bias, float* __restrict__ Z)
{
    __shared__ __align__(16) float As[16][68];
    __shared__ __align__(16) float Bs[16][64];
    const int tid = threadIdx.x;
    const int tx = tid & 15, ty = tid >> 4;
    const int row0 = blockIdx.y * 64, col0 = blockIdx.x * 64;
    float4 pa[2], pb[2];
#pragma unroll
    for (int j = 0; j < 2; j++) {
        int c = tid + j * 128;
        pa[j] = ldf4(A + (size_t)(row0 + (c >> 2)) * 1024 + (c & 3) * 4);
        pb[j] = ldf4(W + (size_t)(c >> 4) * 512 + col0 + (c & 15) * 4);
    }
#pragma unroll
    for (int j = 0; j < 2; j++) {
        int c = tid + j * 128;
        int m = c >> 2, kb = (c & 3) * 4;
        As[kb + 0][m] = pa[j].x; As[kb + 1][m] = pa[j].y;
        As[kb + 2][m] = pa[j].z; As[kb + 3][m] = pa[j].w;
        *reinterpret_cast<float4*>(&Bs[c >> 4][(c & 15) * 4]) = pb[j];
    }
    __syncthreads();
    float acc[8][4];
#pragma unroll
    for (int r = 0; r < 8; r++)
#pragma unroll
        for (int c2 = 0; c2 < 4; c2++) acc[r][c2] = 0.0f;
    for (int k0 = 16;; k0 += 16) {
        const bool more = (k0 < 1024);
        if (more) {
#pragma unroll
            for (int j = 0; j < 2; j++) {
                int c = tid + j * 128;
                pa[j] = ldf4(A + (size_t)(row0 + (c >> 2)) * 1024 + k0 + (c & 3) * 4);
                pb[j] = ldf4(W + (size_t)(k0 + (c >> 4)) * 512 + col0 + (c & 15) * 4);
            }
        }
#pragma unroll
        for (int kk = 0; kk < 16; kk++) {
            float4 a0 = ldf4(&As[kk][ty * 8]);
            float4 a1 = ldf4(&As[kk][ty * 8 + 4]);
            float4 b  = ldf4(&Bs[kk][tx * 4]);
            float av[8] = {a0.x, a0.y, a0.z, a0.w, a1.x, a1.y, a1.z, a1.w};
            float bv[4] = {b.x, b.y, b.z, b.w};
#pragma unroll
            for (int r = 0; r < 8; r++)
#pragma unroll
                for (int c2 = 0; c2 < 4; c2++)
                    acc[r][c2] = fmaf(av[r], bv[c2], acc[r][c2]);
        }
        if (!more) break;
        __syncthreads();
#pragma unroll
        for (int j = 0; j < 2; j++) {
            int c = tid + j * 128;
            int m = c >> 2, kb = (c & 3) * 4;
            As[kb + 0][m] = pa[j].x; As[kb + 1][m] = pa[j].y;
            As[kb + 2][m] = pa[j].z; As[kb + 3][m] = pa[j].w;
            *reinterpret_cast<float4*>(&Bs[c >> 4][(c & 15) * 4]) = pb[j];
        }
        __syncthreads();
    }
    float4 bv4 = ldf4(bias + col0 + tx * 4);
#pragma unroll
    for (int r = 0; r < 8; r++) {
        float4 v = make_float4(acc[r][0] + bv4.x, acc[r][1] + bv4.y,
                               acc[r][2] + bv4.z, acc[r][3] + bv4.w);
        *reinterpret_cast<float4*>(Z + (size_t)(row0 + ty * 8 + r) * 512 + col0 + tx * 4) = v;
    }
}

// argmax (first-occurrence) + logits emission (validated R4-R13).
__global__ void emit_kernel(const float* __restrict__ logits,
                            float* __restrict__ out, long long out_size)
{
    int row = blockIdx.x, tid = threadIdx.x;
    const float* lr = logits + (size_t)row * 512;
    float best = -3.402823466e38f; int bi = 0;
#pragma unroll
    for (int j = 0; j < 4; j++) {
        int vi = tid + j * 128; float v = lr[vi];
        if (v > best) { best = v; bi = vi; }
    }
    __shared__ float sv[128]; __shared__ int si[128];
    sv[tid] = best; si[tid] = bi;
    __syncthreads();
    for (int s = 64; s > 0; s >>= 1) {
        if (tid < s) {
            float v2 = sv[tid + s]; int i2 = si[tid + s];
            if (v2 > sv[tid] || (v2 == sv[tid] && i2 < si[tid])) { sv[tid] = v2; si[tid] = i2; }
        }
        __syncthreads();
    }
    int amax = si[0];
    if (out_size == BT_LL + BTV_LL) {
        if (tid == 0) out[row] = (float)amax;
        float* lo = out + BT_LL + (size_t)row * 512;
#pragma unroll
        for (int j = 0; j < 4; j++) lo[tid + j * 128] = lr[tid + j * 128];
    } else if (out_size == BTV_LL) {
        float* lo = out + (size_t)row * 512;
#pragma unroll
        for (int j = 0; j < 4; j++) lo[tid + j * 128] = lr[tid + j * 128];
    } else if (out_size == BT_LL) {
        if (tid == 0) reinterpret_cast<int*>(out)[row] = amax;
    } else {
        if (tid == 0 && (long long)row < out_size) out[row] = (float)amax;
#pragma unroll
        for (int j = 0; j < 4; j++) {
            long long o = BT_LL + (long long)row * 512 + tid + j * 128;
            if (o < out_size) out[o] = lr[tid + j * 128];
        }
    }
}

extern "C" void kernel_launch(void* const* d_in, const int* in_sizes, int n_in,
                              void* d_out, int out_size)
{
    Params p;
    const int* tokens = (const int*)d_in[0];
    const float* emb  = (const float*)d_in[1];
    for (int l = 0; l < 6; l++) {
        p.Wx[l] = (const float*)d_in[2 + l * 3];
        p.Wh[l] = (const float*)d_in[3 + l * 3];
        p.b[l]  = (const float*)d_in[4 + l * 3];
    }
    p.w_mean  = (const float*)d_in[20];
    p.b_mean  = (const float*)d_in[21];
    p.w_sigma = (const float*)d_in[22];
    p.b_sigma = (const float*)d_in[23];
    const float* dec_w = (const float*)d_in[24];
    const float* dec_b = (const float*)d_in[25];
    p.eps = (const float*)d_in[26];

    float *y, *lg;
    cudaGetSymbolAddress((void**)&y,  g_y);
    cudaGetSymbolAddress((void**)&lg, g_logits);

    prep_x<<<16384, 256>>>(tokens, emb);
    vae_persistent<<<NBLK, 256>>>(p);
    logits_gemm<<<dim3(8, 512), 128>>>(y, dec_w, dec_b, lg);
    emit_kernel<<<32768, 128>>>(lg, (float*)d_out, (long long)out_size);
}